// round 4
// baseline (speedup 1.0000x reference)
#include <cuda_runtime.h>
#include <cuda_fp16.h>
#include <cstdint>

// Problem shape (fixed by the dataset)
#define M_TOT   64
#define K_TOT   4096
#define O_TOT   11008
#define GROUP   128
#define NGRP    (K_TOT / GROUP)        // 32
#define GPACK   ((NGRP + 7) / 8)       // 4

// Tiling
#define BN      32          // outputs per block -> grid 344 -> 2 blocks/SM
#define BK      128         // K chunk = one quant group
#define NCH     (K_TOT / BK)           // 32
#define PADH    8           // halfs of padding; row stride stays 16B-multiple
#define XSTR    (BK + PADH)            // 136 halfs
#define NTHREADS 256

#define NXBUF   3           // cp.async x staging depth
#define NWBUF   2           // dequant weight double buffer

// fp16 copy of x, produced once per launch by convert_x_kernel
__device__ __half g_xh[M_TOT * K_TOT];

__global__ __launch_bounds__(256) void convert_x_kernel(const float* __restrict__ x)
{
    int idx = blockIdx.x * blockDim.x + threadIdx.x;   // 0..65535 float4s
    float4 v = ((const float4*)x)[idx];
    __half2* dst = (__half2*)g_xh;
    dst[idx * 2]     = __floats2half2_rn(v.x, v.y);
    dst[idx * 2 + 1] = __floats2half2_rn(v.z, v.w);
}

#define CP_ASYNC16(dst_u32, src_ptr) \
    asm volatile("cp.async.cg.shared.global [%0], [%1], 16;\n" :: "r"(dst_u32), "l"(src_ptr))
#define CP_COMMIT() asm volatile("cp.async.commit_group;\n" ::: "memory")
#define CP_WAIT1()  asm volatile("cp.async.wait_group 1;\n" ::: "memory")

__global__ __launch_bounds__(NTHREADS)
void w4a16_mma_kernel(const int*   __restrict__ qw,
                      const int*   __restrict__ qz,
                      const float* __restrict__ sc,
                      float*       __restrict__ out)
{
    extern __shared__ __half smem[];
    __half (*xs)[M_TOT][XSTR] = (__half (*)[M_TOT][XSTR])smem;                       // [NXBUF][64][136]
    __half (*ws)[BN][XSTR]    = (__half (*)[BN][XSTR])(smem + NXBUF * M_TOT * XSTR); // [NWBUF][32][136]

    const int tid  = threadIdx.x;
    const int warp = tid >> 5;
    const int lane = tid & 31;
    const int nBase = blockIdx.x * BN;

    // Warp tiling: 4 warps along M (16 rows each), 2 warps along N (16 cols each)
    const int wm = (warp & 3) * 16;
    const int wn = (warp >> 2) * 16;

    const int grp = lane >> 2;   // 0..7
    const int tq  = lane & 3;    // 0..3

    // x staging assignment: thread -> (row m, quarter q) ; 4 x 16B cp.async
    const int xm = tid >> 2;
    const int xq = tid & 3;

    // weight staging: thread -> (row 0..31, word-pair 0..7)
    const int wrow  = tid >> 3;
    const int wpair = tid & 7;
    const int wo    = nBase + wrow;

    float acc[2][4];
    #pragma unroll
    for (int j = 0; j < 2; j++)
        #pragma unroll
        for (int r = 0; r < 4; r++) acc[j][r] = 0.0f;

    // ---- staging registers for weights ----
    uint2   qr;
    __half2 s2r;
    int     zr;

    auto cpasync_x = [&](int chunk) {
        int buf = chunk % NXBUF;
        const __half* src = g_xh + xm * K_TOT + chunk * BK + xq * 32;
        unsigned dst = (unsigned)__cvta_generic_to_shared(&xs[buf][xm][xq * 32]);
        #pragma unroll
        for (int j = 0; j < 4; j++)
            CP_ASYNC16(dst + j * 16, src + j * 8);
    };

    auto load_w = [&](int chunk) {
        int kb = chunk * BK;
        qr = *(const uint2*)(qw + wo * (K_TOT / 8) + (kb >> 3) + wpair * 2);
        unsigned zw = (unsigned)qz[wo * GPACK + (chunk >> 3)];
        zr  = (int)((zw >> ((chunk & 7) * 4)) & 15u);
        s2r = __half2half2(__float2half_rn(sc[wo * NGRP + chunk]));
    };

    auto store_w = [&](int chunk) {
        int buf = chunk % NWBUF;
        const unsigned wv[2] = {qr.x, qr.y};
        #pragma unroll
        for (int j = 0; j < 2; j++) {
            unsigned w32 = wv[j];
            __half2 vals[4];
            #pragma unroll
            for (int p = 0; p < 4; p++) {
                int q0 = (int)((w32 >> (8 * p))     & 15u);
                int q1 = (int)((w32 >> (8 * p + 4)) & 15u);
                vals[p] = __hmul2(__halves2half2(__int2half_rn(q0 - zr),
                                                 __int2half_rn(q1 - zr)), s2r);
            }
            *(uint4*)(&ws[buf][wrow][(wpair * 2 + j) * 8]) = *(uint4*)vals;
        }
    };

    // ---- prologue ----
    cpasync_x(0); CP_COMMIT();
    cpasync_x(1); CP_COMMIT();
    load_w(0);
    store_w(0);          // one-time LDG stall
    load_w(1);           // in flight across chunk 0's MMA

    for (int i = 0; i < NCH; i++) {
        CP_WAIT1();              // x chunk i landed (group g_i drained)
        __syncthreads();         // ws(i) stores + x(i) visible to all warps

        // prefetch x chunk i+2 into buf (i+2)%3 (its last readers finished at this barrier)
        if (i + 2 < NCH) cpasync_x(i + 2);
        CP_COMMIT();             // unconditional: keeps group accounting uniform

        const int xb = i % NXBUF;
        const int wb = i % NWBUF;

        // ---- MMA over chunk i ----
        #pragma unroll
        for (int kk = 0; kk < BK; kk += 16) {
            unsigned a[4];
            {
                int row0 = wm + grp;
                int c0   = kk + tq * 2;
                a[0] = *(const unsigned*)(&xs[xb][row0    ][c0    ]);
                a[1] = *(const unsigned*)(&xs[xb][row0 + 8][c0    ]);
                a[2] = *(const unsigned*)(&xs[xb][row0    ][c0 + 8]);
                a[3] = *(const unsigned*)(&xs[xb][row0 + 8][c0 + 8]);
            }
            unsigned b[2][2];
            #pragma unroll
            for (int nt = 0; nt < 2; nt++) {
                int col = wn + nt * 8 + grp;
                int k0  = kk + tq * 2;
                b[nt][0] = *(const unsigned*)(&ws[wb][col][k0    ]);
                b[nt][1] = *(const unsigned*)(&ws[wb][col][k0 + 8]);
            }
            #pragma unroll
            for (int nt = 0; nt < 2; nt++)
                asm volatile(
                    "mma.sync.aligned.m16n8k16.row.col.f32.f16.f16.f32 "
                    "{%0,%1,%2,%3}, {%4,%5,%6,%7}, {%8,%9}, {%0,%1,%2,%3};\n"
                    : "+f"(acc[nt][0]), "+f"(acc[nt][1]),
                      "+f"(acc[nt][2]), "+f"(acc[nt][3])
                    : "r"(a[0]), "r"(a[1]), "r"(a[2]), "r"(a[3]),
                      "r"(b[nt][0]), "r"(b[nt][1]));
        }

        // dequant chunk i+1 into the other ws buffer (nobody reads it right now)
        if (i + 1 < NCH) store_w(i + 1);
        if (i + 2 < NCH) load_w(i + 2);   // LDG has all of MMA(i+1) to land
    }

    // ---- epilogue ----
    #pragma unroll
    for (int nt = 0; nt < 2; nt++) {
        int row = wm + grp;
        int col = nBase + wn + nt * 8 + tq * 2;
        out[row * O_TOT + col]           = acc[nt][0];
        out[row * O_TOT + col + 1]       = acc[nt][1];
        out[(row + 8) * O_TOT + col]     = acc[nt][2];
        out[(row + 8) * O_TOT + col + 1] = acc[nt][3];
    }
}

extern "C" void kernel_launch(void* const* d_in, const int* in_sizes, int n_in,
                              void* d_out, int out_size)
{
    const float* x  = (const float*)d_in[0];   // [64, 4096] (fp16 upcast to fp32)
    const int*   qw = (const int*)  d_in[1];   // [11008, 512] int32
    const int*   qz = (const int*)  d_in[2];   // [11008, 4]   int32
    const float* sc = (const float*)d_in[3];   // [11008, 32]  (fp16 upcast to fp32)
    float*       out = (float*)d_out;          // [64, 11008]  fp32

    const int smem_bytes = (NXBUF * M_TOT * XSTR + NWBUF * BN * XSTR) * (int)sizeof(__half);
    cudaFuncSetAttribute(w4a16_mma_kernel,
                         cudaFuncAttributeMaxDynamicSharedMemorySize, smem_bytes);

    convert_x_kernel<<<256, 256>>>(x);                       // 65536 float4 -> fp16
    w4a16_mma_kernel<<<O_TOT / BN, NTHREADS, smem_bytes>>>(qw, qz, sc, (float*)d_out);
}

// round 6
// speedup vs baseline: 1.6604x; 1.6604x over previous
#include <cuda_runtime.h>
#include <cuda_fp16.h>
#include <cstdint>

// Problem shape (fixed by the dataset)
#define M_TOT   64
#define K_TOT   4096
#define O_TOT   11008
#define GROUP   128
#define NGRP    (K_TOT / GROUP)        // 32
#define GPACK   ((NGRP + 7) / 8)       // 4

// Tiling
#define BN      64          // outputs per block
#define BK      128         // K chunk = one quant group
#define KSPLIT  2           // split-K factor -> grid (172, 2) -> 2 blocks/SM
#define NCHS    (K_TOT / BK / KSPLIT)  // 16 chunks per block
#define PADH    8
#define XSTR    (BK + PADH)            // 136 halfs row stride
#define NTHREADS 256

// fp16 copy of x, produced once per launch
__device__ __half g_xh[M_TOT * K_TOT];

__global__ __launch_bounds__(256) void convert_x_kernel(const float* __restrict__ x)
{
    int idx = blockIdx.x * blockDim.x + threadIdx.x;   // 65536 float4s
    float4 v = ((const float4*)x)[idx];
    __half2* dst = (__half2*)g_xh;
    dst[idx * 2]     = __floats2half2_rn(v.x, v.y);
    dst[idx * 2 + 1] = __floats2half2_rn(v.z, v.w);
}

__global__ __launch_bounds__(256) void zero_out_kernel(float* __restrict__ out)
{
    int idx = blockIdx.x * blockDim.x + threadIdx.x;   // 176128 float4s
    ((float4*)out)[idx] = make_float4(0.f, 0.f, 0.f, 0.f);
}

__global__ __launch_bounds__(NTHREADS)
void w4a16_mma_kernel(const int*   __restrict__ qw,
                      const int*   __restrict__ qz,
                      const float* __restrict__ sc,
                      float*       __restrict__ out)
{
    __shared__ __half xs[M_TOT][XSTR];   // 64 x 136
    __shared__ __half ws[BN][XSTR];      // 64 x 136

    const int tid  = threadIdx.x;
    const int warp = tid >> 5;
    const int lane = tid & 31;
    const int nBase = blockIdx.x * BN;
    const int cBase = blockIdx.y * NCHS;     // first chunk (== group) of this split

    // Warp tiling: 2 warps along M (32 rows), 4 warps along N (16 cols)
    const int wm = (warp & 1) * 32;
    const int wn = (warp >> 1) * 16;

    const int grp = lane >> 2;   // 0..7
    const int tq  = lane & 3;    // 0..3

    // x staging: thread -> one uint4 (8 halfs) x 4 rounds
    // weight staging: thread -> 4 contiguous qwords of one row
    const int wrow = tid >> 2;               // 0..63
    const int wseg = tid & 3;                // 0..3
    const int wo   = nBase + wrow;

    float acc[2][2][4];
    #pragma unroll
    for (int i = 0; i < 2; i++)
        #pragma unroll
        for (int j = 0; j < 2; j++)
            #pragma unroll
            for (int r = 0; r < 4; r++) acc[i][j][r] = 0.0f;

    // staging registers
    uint4   xr[4];      // 4 x 8 halfs of x
    uint4   qr;         // 32 int4 weights of one row
    __half2 s2r;
    int     zr;

    auto load_stage = [&](int c) {            // c = absolute chunk/group index
        const int kb = c * BK;
        #pragma unroll
        for (int r = 0; r < 4; r++) {
            int idx = tid + r * NTHREADS;     // 0..1023
            int m   = idx >> 4;               // 16 uint4 per 128-half row
            int col = idx & 15;
            xr[r] = *(const uint4*)(g_xh + m * K_TOT + kb + col * 8);
        }
        qr = *(const uint4*)(qw + wo * (K_TOT / 8) + (kb >> 3) + wseg * 4);
        unsigned zw = (unsigned)qz[wo * GPACK + (c >> 3)];
        zr  = (int)((zw >> ((c & 7) * 4)) & 15u);
        s2r = __half2half2(__float2half_rn(sc[wo * NGRP + c]));
    };

    auto store_stage = [&]() {
        #pragma unroll
        for (int r = 0; r < 4; r++) {
            int idx = tid + r * NTHREADS;
            int m   = idx >> 4;
            int col = idx & 15;
            *(uint4*)(&xs[m][col * 8]) = xr[r];
        }
        const unsigned wv[4] = {qr.x, qr.y, qr.z, qr.w};
        #pragma unroll
        for (int j = 0; j < 4; j++) {
            unsigned w32 = wv[j];
            __half2 vals[4];
            #pragma unroll
            for (int p = 0; p < 4; p++) {
                int q0 = (int)((w32 >> (8 * p))     & 15u);
                int q1 = (int)((w32 >> (8 * p + 4)) & 15u);
                vals[p] = __hmul2(__halves2half2(__int2half_rn(q0 - zr),
                                                 __int2half_rn(q1 - zr)), s2r);
            }
            *(uint4*)(&ws[wrow][(wseg * 4 + j) * 8]) = *(uint4*)vals;
        }
    };

    load_stage(cBase);
    store_stage();

    for (int i = 0; i < NCHS; i++) {
        __syncthreads();                     // tile i ready

        if (i + 1 < NCHS) load_stage(cBase + i + 1);   // LDGs fly during MMA

        #pragma unroll
        for (int kk = 0; kk < BK; kk += 16) {
            unsigned a[2][4];
            #pragma unroll
            for (int mt = 0; mt < 2; mt++) {
                int row0 = wm + mt * 16 + grp;
                int c0   = kk + tq * 2;
                a[mt][0] = *(const unsigned*)(&xs[row0    ][c0    ]);
                a[mt][1] = *(const unsigned*)(&xs[row0 + 8][c0    ]);
                a[mt][2] = *(const unsigned*)(&xs[row0    ][c0 + 8]);
                a[mt][3] = *(const unsigned*)(&xs[row0 + 8][c0 + 8]);
            }
            unsigned b[2][2];
            #pragma unroll
            for (int nt = 0; nt < 2; nt++) {
                int col = wn + nt * 8 + grp;
                int k0  = kk + tq * 2;
                b[nt][0] = *(const unsigned*)(&ws[col][k0    ]);
                b[nt][1] = *(const unsigned*)(&ws[col][k0 + 8]);
            }
            #pragma unroll
            for (int mt = 0; mt < 2; mt++)
                #pragma unroll
                for (int nt = 0; nt < 2; nt++)
                    asm volatile(
                        "mma.sync.aligned.m16n8k16.row.col.f32.f16.f16.f32 "
                        "{%0,%1,%2,%3}, {%4,%5,%6,%7}, {%8,%9}, {%0,%1,%2,%3};\n"
                        : "+f"(acc[mt][nt][0]), "+f"(acc[mt][nt][1]),
                          "+f"(acc[mt][nt][2]), "+f"(acc[mt][nt][3])
                        : "r"(a[mt][0]), "r"(a[mt][1]), "r"(a[mt][2]), "r"(a[mt][3]),
                          "r"(b[nt][0]), "r"(b[nt][1]));
        }

        __syncthreads();                     // all warps done with tile i

        if (i + 1 < NCHS) store_stage();     // waits on LDG here
    }

    // ---- epilogue: accumulate split partials ----
    #pragma unroll
    for (int mt = 0; mt < 2; mt++) {
        #pragma unroll
        for (int nt = 0; nt < 2; nt++) {
            int row = wm + mt * 16 + grp;
            int col = nBase + wn + nt * 8 + tq * 2;
            atomicAdd(&out[row * O_TOT + col],           acc[mt][nt][0]);
            atomicAdd(&out[row * O_TOT + col + 1],       acc[mt][nt][1]);
            atomicAdd(&out[(row + 8) * O_TOT + col],     acc[mt][nt][2]);
            atomicAdd(&out[(row + 8) * O_TOT + col + 1], acc[mt][nt][3]);
        }
    }
}

extern "C" void kernel_launch(void* const* d_in, const int* in_sizes, int n_in,
                              void* d_out, int out_size)
{
    const float* x  = (const float*)d_in[0];   // [64, 4096] (fp16 upcast to fp32)
    const int*   qw = (const int*)  d_in[1];   // [11008, 512] int32
    const int*   qz = (const int*)  d_in[2];   // [11008, 4]   int32
    const float* sc = (const float*)d_in[3];   // [11008, 32]  (fp16 upcast to fp32)
    float*       out = (float*)d_out;          // [64, 11008]  fp32

    zero_out_kernel<<<(M_TOT * O_TOT / 4 + 255) / 256, 256>>>(out);   // 176128 float4
    convert_x_kernel<<<256, 256>>>(x);

    dim3 grid(O_TOT / BN, KSPLIT);   // (172, 2)
    w4a16_mma_kernel<<<grid, NTHREADS>>>(qw, qz, sc, out);
}